// round 10
// baseline (speedup 1.0000x reference)
#include <cuda_runtime.h>
#include <cuda_fp16.h>
#include <cstdint>

#define BDIM 16
#define NDIM 128
#define HDIM 256

#define ASTR 264     // A smem row stride (fp16), padded: ldmatrix conflict-free
#define BSTR 40      // B smem row stride (fp16): 32 n-cols + 8 pad

#define A_BYTES (128 * ASTR * 2)          // 67584
#define B_BYTES (256 * BSTR * 2)          // 20480 per buffer
#define MISC_OFF (A_BYTES + 2 * B_BYTES)  // 108544 (double-buffered B)
#define SMEM_REQ (MISC_OFF + 3712)        // misc needs 3616B -> 112256 total

#define NTHR 256

// scratch
__device__ float  g_xw [BDIM * NDIM * HDIM];           // inputs @ W_atom (fp32)
__device__ __align__(16) __half g_xwh[BDIM * NDIM * HDIM];  // fp16 image of xw
__device__ __align__(16) __half g_Wf[HDIM * HDIM];     // fp16 image of W_bin

// ---------------------------------------------------------------------------
__device__ __forceinline__ uint32_t smem_u32(const void* p) {
    uint32_t a;
    asm("{ .reg .u64 t; cvta.to.shared.u64 t, %1; cvt.u32.u64 %0, t; }" : "=r"(a) : "l"(p));
    return a;
}
__device__ __forceinline__ void cp_async16(uint32_t dst, const void* src) {
    asm volatile("cp.async.cg.shared.global [%0], [%1], 16;" :: "r"(dst), "l"(src));
}
__device__ __forceinline__ void ldsm_x4(uint32_t* r, uint32_t addr) {
    asm volatile("ldmatrix.sync.aligned.m8n8.x4.shared.b16 {%0,%1,%2,%3}, [%4];"
        : "=r"(r[0]), "=r"(r[1]), "=r"(r[2]), "=r"(r[3]) : "r"(addr));
}
__device__ __forceinline__ void ldsm_x4_t(uint32_t* r, uint32_t addr) {
    asm volatile("ldmatrix.sync.aligned.m8n8.x4.trans.shared.b16 {%0,%1,%2,%3}, [%4];"
        : "=r"(r[0]), "=r"(r[1]), "=r"(r[2]), "=r"(r[3]) : "r"(addr));
}
__device__ __forceinline__ void mma16816(float* d, const uint32_t* a, const uint32_t* b) {
    asm volatile("mma.sync.aligned.m16n8k16.row.col.f32.f16.f16.f32 "
        "{%0,%1,%2,%3}, {%4,%5,%6,%7}, {%8,%9}, {%0,%1,%2,%3};"
        : "+f"(d[0]), "+f"(d[1]), "+f"(d[2]), "+f"(d[3])
        : "r"(a[0]), "r"(a[1]), "r"(a[2]), "r"(a[3]), "r"(b[0]), "r"(b[1]));
}
__device__ __forceinline__ float4 ldcs4(const float4* p) {
    float4 v;
    asm volatile("ld.global.cs.v4.f32 {%0,%1,%2,%3}, [%4];"
        : "=f"(v.x), "=f"(v.y), "=f"(v.z), "=f"(v.w) : "l"(p));
    return v;
}
__device__ __forceinline__ void stcs4(float4* p, float4 v) {
    asm volatile("st.global.cs.v4.f32 [%0], {%1,%2,%3,%4};"
        :: "l"(p), "f"(v.x), "f"(v.y), "f"(v.z), "f"(v.w));
}

// ---------------------------------------------------------------------------
// Kernel 1: xw[b,n,k] = sum_h inputs[b,n,h] * W_atom[h,k]  (fp32 + fp16 image)
// ---------------------------------------------------------------------------
__global__ void __launch_bounds__(256, 4) xw_kernel(
    const float* __restrict__ inputs, const float* __restrict__ W_atom)
{
    __shared__ float s_in[4][HDIM];
    int row0 = blockIdx.x * 4;
    int t = threadIdx.x;
#pragma unroll
    for (int r = 0; r < 4; r++) s_in[r][t] = inputs[(row0 + r) * HDIM + t];
    __syncthreads();

    float a0 = 0.f, a1 = 0.f, a2 = 0.f, a3 = 0.f;
#pragma unroll 8
    for (int h = 0; h < HDIM; h++) {
        float w = W_atom[h * HDIM + t];
        a0 = fmaf(s_in[0][h], w, a0);
        a1 = fmaf(s_in[1][h], w, a1);
        a2 = fmaf(s_in[2][h], w, a2);
        a3 = fmaf(s_in[3][h], w, a3);
    }
    g_xw[(row0 + 0) * HDIM + t] = a0;
    g_xw[(row0 + 1) * HDIM + t] = a1;
    g_xw[(row0 + 2) * HDIM + t] = a2;
    g_xw[(row0 + 3) * HDIM + t] = a3;
    g_xwh[(row0 + 0) * HDIM + t] = __float2half_rn(a0);
    g_xwh[(row0 + 1) * HDIM + t] = __float2half_rn(a1);
    g_xwh[(row0 + 2) * HDIM + t] = __float2half_rn(a2);
    g_xwh[(row0 + 3) * HDIM + t] = __float2half_rn(a3);
}

// ---------------------------------------------------------------------------
// Kernel 2: W_bin fp32 -> fp16 image (packed [h][n])
// ---------------------------------------------------------------------------
__global__ void __launch_bounds__(256) prep_w(const float* __restrict__ W_bin)
{
    int f = blockIdx.x * 256 + threadIdx.x;   // 0..16383 float4
    float4 v = *(const float4*)&W_bin[f * 4];
    __half2 p0 = __floats2half2_rn(v.x, v.y);
    __half2 p1 = __floats2half2_rn(v.z, v.w);
    *(uint2*)&g_Wf[f * 4] = make_uint2(*(uint32_t*)&p0, *(uint32_t*)&p1);
}

// ---------------------------------------------------------------------------
// Kernel 3: one CTA per (b,i). 8 warps m16 x n32, 2 CTAs/SM,
//           double-buffered B chunks (1 sync/chunk, prefetch overlapped).
// ---------------------------------------------------------------------------
extern __shared__ unsigned char smraw[];

__global__ void __launch_bounds__(NTHR, 2) main_kernel(
    const float* __restrict__ inputs,
    const float* __restrict__ bin_features,
    const float* __restrict__ b_bin,
    const float* __restrict__ w_score,
    const float* __restrict__ b_score,
    float* __restrict__ out_ctx,
    float* __restrict__ out_pair)
{
    const int bi   = blockIdx.x;         // b*128 + i
    const int b    = bi >> 7;
    const int t    = threadIdx.x;
    const int warp = t >> 5;             // 0..7  (16 j-rows each)
    const int lane = t & 31;
    const int g4   = lane >> 2, t4 = lane & 3;

    __half* A_s = (__half*)smraw;                  // [128][ASTR]
    float* base_s  = (float*)(smraw + MISC_OFF);   // xw_i + b_bin  [256]
    float* wsc_s   = base_s + HDIM;                // w_score       [256]
    float* ini_s   = wsc_s + HDIM;                 // inputs[b,i,:] [256]
    float* score_s = ini_s + HDIM;                 // [128]
    float* red_s   = score_s + NDIM;               // [8]

    const uint32_t sbase = smem_u32(smraw);
    const uint32_t sA = sbase;
    const uint32_t sB[2] = { sbase + A_BYTES, sbase + A_BYTES + B_BYTES };

    // --- issue B chunk 0 prefetch first (overlaps A convert) ---
#pragma unroll
    for (int it = 0; it < 4; it++) {
        int idx = t + it * NTHR;     // 0..1023
        int h = idx >> 2, seg = idx & 3;
        cp_async16(sB[0] + (uint32_t)(h * BSTR + seg * 8) * 2,
                   &g_Wf[h * HDIM + 0 * 32 + seg * 8]);
    }
    asm volatile("cp.async.commit_group;" ::: "memory");

    // small smem fills
    base_s[t] = g_xw[bi * HDIM + t] + b_bin[t];
    wsc_s[t]  = w_score[t];
    ini_s[t]  = inputs[bi * HDIM + t];

    // A: bin[b,i] fp32 -> fp16 into padded smem (streaming loads)
    const float4* gA = (const float4*)(bin_features + (size_t)bi * NDIM * HDIM);
#pragma unroll
    for (int r = 0; r < 32; r++) {
        int f = t + r * NTHR;            // 0..8191 float4
        int j = f >> 6, q = f & 63;
        float4 v = ldcs4(&gA[f]);
        __half2 p0 = __floats2half2_rn(v.x, v.y);
        __half2 p1 = __floats2half2_rn(v.z, v.w);
        *(uint2*)&A_s[j * ASTR + q * 4] = make_uint2(*(uint32_t*)&p0, *(uint32_t*)&p1);
    }

    __syncthreads();   // ini_s/base_s/wsc_s (and A) visible to ALL threads

    const float4* gin  = (const float4*)(inputs + (size_t)b * NDIM * HDIM);
    float4*       gpr  = (float4*)(out_pair + (size_t)bi * NDIM * HDIM);
    const float4* ini4 = (const float4*)ini_s;
    const __half* xwbh = g_xwh + (size_t)(b * NDIM) * HDIM;

    const uint32_t a_lane = (uint32_t)(((warp * 16 + (lane & 15)) * ASTR + ((lane >> 4) << 3)) * 2);
    const uint32_t b_lane = (uint32_t)(((lane & 15) * BSTR + ((lane >> 4) << 3)) * 2);

    // per-warp running scores for two j rows
    float sc0 = 0.f, sc1 = 0.f;
    const int j0 = warp * 16 + g4;
    const int j1 = j0 + 8;

    for (int c = 0; c < 8; c++) {
        // atom_pair: this chunk's eighth of the 128KB write (overlaps)
#pragma unroll
        for (int r = 0; r < 4; r++) {
            int g = (c << 10) + t + r * NTHR;
            int j = g >> 6, q = g & 63;
            float4 a = ini4[q];
            float4 x = gin[(j << 6) + q];
            a.x += x.x; a.y += x.y; a.z += x.z; a.w += x.w;
            stcs4(&gpr[g], a);
        }

        asm volatile("cp.async.wait_group 0;" ::: "memory");
        __syncthreads();   // B[c] visible to all; all warps done with chunk c-1

        // prefetch B chunk c+1 into the other buffer (flies during MMA)
        if (c < 7) {
            const uint32_t dstB = sB[(c + 1) & 1];
#pragma unroll
            for (int it = 0; it < 4; it++) {
                int idx = t + it * NTHR;
                int h = idx >> 2, seg = idx & 3;
                cp_async16(dstB + (uint32_t)(h * BSTR + seg * 8) * 2,
                           &g_Wf[h * HDIM + (c + 1) * 32 + seg * 8]);
            }
            asm volatile("cp.async.commit_group;" ::: "memory");
        }

        const uint32_t curB = sB[c & 1];
        float acc[4][4];
#pragma unroll
        for (int tn = 0; tn < 4; tn++)
#pragma unroll
            for (int e = 0; e < 4; e++) acc[tn][e] = 0.f;

#pragma unroll 4
        for (int ks = 0; ks < 16; ks++) {
            const int k0 = ks * 16;
            uint32_t av[4], bv[2][4];
            ldsm_x4(av, sA + a_lane + (uint32_t)(k0 * 2));
#pragma unroll
            for (int nt = 0; nt < 2; nt++)
                ldsm_x4_t(bv[nt], curB + b_lane + (uint32_t)((k0 * BSTR + nt * 16) * 2));
#pragma unroll
            for (int tn = 0; tn < 4; tn++) {
                const int nt = tn >> 1, hf = (tn & 1) * 2;
                mma16816(acc[tn], av, &bv[nt][hf]);
            }
        }

        // fused epilogue on fragments (xw via fp16 image)
        const int Cb = c * 32;
        float p0 = 0.f, p1 = 0.f;
#pragma unroll
        for (int tn = 0; tn < 4; tn++) {
            const int n0 = Cb + tn * 8 + t4 * 2;
            float2 bw = *(const float2*)&base_s[n0];
            float2 wv = *(const float2*)&wsc_s[n0];
            float2 x0 = __half22float2(*(const __half2*)&xwbh[(size_t)j0 * HDIM + n0]);
            float2 x1 = __half22float2(*(const __half2*)&xwbh[(size_t)j1 * HDIM + n0]);
            const float* a = acc[tn];
            p0 = fmaf(fmaxf(a[0] + bw.x + x0.x, 0.f), wv.x, p0);
            p0 = fmaf(fmaxf(a[1] + bw.y + x0.y, 0.f), wv.y, p0);
            p1 = fmaf(fmaxf(a[2] + bw.x + x1.x, 0.f), wv.x, p1);
            p1 = fmaf(fmaxf(a[3] + bw.y + x1.y, 0.f), wv.y, p1);
        }
        p0 += __shfl_xor_sync(0xffffffffu, p0, 1);
        p0 += __shfl_xor_sync(0xffffffffu, p0, 2);
        p1 += __shfl_xor_sync(0xffffffffu, p1, 1);
        p1 += __shfl_xor_sync(0xffffffffu, p1, 2);
        sc0 += p0;
        sc1 += p1;
    }

    if (t4 == 0) {
        score_s[j0] = sc0;
        score_s[j1] = sc1;
    }

    __syncthreads();
    if (t < NDIM) {
        float S = score_s[t];
        S += __shfl_xor_sync(0xffffffffu, S, 16);
        S += __shfl_xor_sync(0xffffffffu, S, 8);
        S += __shfl_xor_sync(0xffffffffu, S, 4);
        S += __shfl_xor_sync(0xffffffffu, S, 2);
        S += __shfl_xor_sync(0xffffffffu, S, 1);
        if ((t & 31) == 0) red_s[t >> 5] = S;
    }
    __syncthreads();
    if (t == 0)
        red_s[4] = red_s[0] + red_s[1] + red_s[2] + red_s[3]
                 + (float)NDIM * b_score[0];
    __syncthreads();

    out_ctx[bi * HDIM + t] = ini_s[t] * red_s[4];
}

// ---------------------------------------------------------------------------
extern "C" void kernel_launch(void* const* d_in, const int* in_sizes, int n_in,
                              void* d_out, int out_size)
{
    const float* inputs       = (const float*)d_in[0];
    const float* bin_features = (const float*)d_in[1];
    const float* W_atom       = (const float*)d_in[2];
    const float* W_bin        = (const float*)d_in[3];
    const float* b_bin        = (const float*)d_in[4];
    const float* w_score      = (const float*)d_in[5];
    const float* b_score      = (const float*)d_in[6];

    float* out_ctx  = (float*)d_out;                   // [B,N,H]
    float* out_pair = out_ctx + BDIM * NDIM * HDIM;    // [B,N,N,H]

    static bool attr_set = false;
    if (!attr_set) {
        cudaFuncSetAttribute(main_kernel, cudaFuncAttributeMaxDynamicSharedMemorySize,
                             SMEM_REQ);
        attr_set = true;
    }

    xw_kernel<<<(BDIM * NDIM) / 4, 256>>>(inputs, W_atom);
    prep_w<<<64, 256>>>(W_bin);
    main_kernel<<<BDIM * NDIM, NTHR, SMEM_REQ>>>(
        inputs, bin_features, b_bin, w_score, b_score, out_ctx, out_pair);
}

// round 11
// speedup vs baseline: 1.1867x; 1.1867x over previous
#include <cuda_runtime.h>
#include <cuda_fp16.h>
#include <cstdint>

#define BDIM 16
#define NDIM 128
#define HDIM 256

#define BSTR 40      // B smem row stride (fp16): 32 n-cols + 8 pad

#define B_BYTES (256 * BSTR * 2)          // 20480 per buffer
#define MISC_OFF (2 * B_BYTES)            // 40960 (double-buffered B)
#define SMEM_REQ (MISC_OFF + 3712)        // misc needs 3616B -> 44672 total

#define NTHR 256

// scratch
__device__ float  g_xw [BDIM * NDIM * HDIM];                // inputs @ W_atom (fp32)
__device__ __align__(16) __half g_xwh[BDIM * NDIM * HDIM];  // fp16 image of xw
__device__ __align__(16) __half g_Wf[HDIM * HDIM];          // fp16 image of W_bin

// ---------------------------------------------------------------------------
__device__ __forceinline__ uint32_t smem_u32(const void* p) {
    uint32_t a;
    asm("{ .reg .u64 t; cvta.to.shared.u64 t, %1; cvt.u32.u64 %0, t; }" : "=r"(a) : "l"(p));
    return a;
}
__device__ __forceinline__ void cp_async16(uint32_t dst, const void* src) {
    asm volatile("cp.async.cg.shared.global [%0], [%1], 16;" :: "r"(dst), "l"(src));
}
__device__ __forceinline__ void ldsm_x4_t(uint32_t* r, uint32_t addr) {
    asm volatile("ldmatrix.sync.aligned.m8n8.x4.trans.shared.b16 {%0,%1,%2,%3}, [%4];"
        : "=r"(r[0]), "=r"(r[1]), "=r"(r[2]), "=r"(r[3]) : "r"(addr));
}
__device__ __forceinline__ void mma16816(float* d, const uint32_t* a, const uint32_t* b) {
    asm volatile("mma.sync.aligned.m16n8k16.row.col.f32.f16.f16.f32 "
        "{%0,%1,%2,%3}, {%4,%5,%6,%7}, {%8,%9}, {%0,%1,%2,%3};"
        : "+f"(d[0]), "+f"(d[1]), "+f"(d[2]), "+f"(d[3])
        : "r"(a[0]), "r"(a[1]), "r"(a[2]), "r"(a[3]), "r"(b[0]), "r"(b[1]));
}
__device__ __forceinline__ float4 ldcs4(const float4* p) {
    float4 v;
    asm volatile("ld.global.cs.v4.f32 {%0,%1,%2,%3}, [%4];"
        : "=f"(v.x), "=f"(v.y), "=f"(v.z), "=f"(v.w) : "l"(p));
    return v;
}
__device__ __forceinline__ float2 ldcs2(const float* p) {
    float2 v;
    asm volatile("ld.global.cs.v2.f32 {%0,%1}, [%2];"
        : "=f"(v.x), "=f"(v.y) : "l"(p));
    return v;
}
__device__ __forceinline__ void stcs4(float4* p, float4 v) {
    asm volatile("st.global.cs.v4.f32 [%0], {%1,%2,%3,%4};"
        :: "l"(p), "f"(v.x), "f"(v.y), "f"(v.z), "f"(v.w));
}
__device__ __forceinline__ uint32_t f2h2(float2 v) {
    __half2 h = __floats2half2_rn(v.x, v.y);
    return *(uint32_t*)&h;
}

// ---------------------------------------------------------------------------
// Kernel 1: xw[b,n,k] = sum_h inputs[b,n,h] * W_atom[h,k]  (fp32 + fp16 image)
// ---------------------------------------------------------------------------
__global__ void __launch_bounds__(256, 4) xw_kernel(
    const float* __restrict__ inputs, const float* __restrict__ W_atom)
{
    __shared__ float s_in[4][HDIM];
    int row0 = blockIdx.x * 4;
    int t = threadIdx.x;
#pragma unroll
    for (int r = 0; r < 4; r++) s_in[r][t] = inputs[(row0 + r) * HDIM + t];
    __syncthreads();

    float a0 = 0.f, a1 = 0.f, a2 = 0.f, a3 = 0.f;
#pragma unroll 8
    for (int h = 0; h < HDIM; h++) {
        float w = W_atom[h * HDIM + t];
        a0 = fmaf(s_in[0][h], w, a0);
        a1 = fmaf(s_in[1][h], w, a1);
        a2 = fmaf(s_in[2][h], w, a2);
        a3 = fmaf(s_in[3][h], w, a3);
    }
    g_xw[(row0 + 0) * HDIM + t] = a0;
    g_xw[(row0 + 1) * HDIM + t] = a1;
    g_xw[(row0 + 2) * HDIM + t] = a2;
    g_xw[(row0 + 3) * HDIM + t] = a3;
    g_xwh[(row0 + 0) * HDIM + t] = __float2half_rn(a0);
    g_xwh[(row0 + 1) * HDIM + t] = __float2half_rn(a1);
    g_xwh[(row0 + 2) * HDIM + t] = __float2half_rn(a2);
    g_xwh[(row0 + 3) * HDIM + t] = __float2half_rn(a3);
}

// ---------------------------------------------------------------------------
// Kernel 2: W_bin fp32 -> fp16 image (packed [h][n])
// ---------------------------------------------------------------------------
__global__ void __launch_bounds__(256) prep_w(const float* __restrict__ W_bin)
{
    int f = blockIdx.x * 256 + threadIdx.x;   // 0..16383 float4
    float4 v = *(const float4*)&W_bin[f * 4];
    __half2 p0 = __floats2half2_rn(v.x, v.y);
    __half2 p1 = __floats2half2_rn(v.z, v.w);
    *(uint2*)&g_Wf[f * 4] = make_uint2(*(uint32_t*)&p0, *(uint32_t*)&p1);
}

// ---------------------------------------------------------------------------
// Kernel 3: one CTA per (b,i). 8 warps m16 x n32, 2 CTAs/SM.
//   A kept ENTIRELY in registers (fragment-layout global loads, no A smem).
// ---------------------------------------------------------------------------
extern __shared__ unsigned char smraw[];

__global__ void __launch_bounds__(NTHR, 2) main_kernel(
    const float* __restrict__ inputs,
    const float* __restrict__ bin_features,
    const float* __restrict__ b_bin,
    const float* __restrict__ w_score,
    const float* __restrict__ b_score,
    float* __restrict__ out_ctx,
    float* __restrict__ out_pair)
{
    const int bi   = blockIdx.x;         // b*128 + i
    const int b    = bi >> 7;
    const int t    = threadIdx.x;
    const int warp = t >> 5;             // 0..7  (16 j-rows each)
    const int lane = t & 31;
    const int g4   = lane >> 2, t4 = lane & 3;

    float* base_s  = (float*)(smraw + MISC_OFF);   // xw_i + b_bin  [256]
    float* wsc_s   = base_s + HDIM;                // w_score       [256]
    float* ini_s   = wsc_s + HDIM;                 // inputs[b,i,:] [256]
    float* score_s = ini_s + HDIM;                 // [128]
    float* red_s   = score_s + NDIM;               // [8]

    const uint32_t sbase = smem_u32(smraw);
    const uint32_t sB[2] = { sbase, sbase + B_BYTES };

    // --- issue B chunk 0 prefetch first (overlaps A fragment loads) ---
#pragma unroll
    for (int it = 0; it < 4; it++) {
        int idx = t + it * NTHR;     // 0..1023
        int h = idx >> 2, seg = idx & 3;
        cp_async16(sB[0] + (uint32_t)(h * BSTR + seg * 8) * 2,
                   &g_Wf[h * HDIM + 0 * 32 + seg * 8]);
    }
    asm volatile("cp.async.commit_group;" ::: "memory");

    // small smem fills
    base_s[t] = g_xw[bi * HDIM + t] + b_bin[t];
    wsc_s[t]  = w_score[t];
    ini_s[t]  = inputs[bi * HDIM + t];

    // A fragments: direct global->register loads in mma layout (fp32->fp16).
    // Lane holds, per k16-step ks: a0=(g4, 2t4..+1|k0), a1=(g4+8, |k0),
    //                              a2=(g4, |k0+8),      a3=(g4+8, |k0+8)
    uint32_t afrag[64];
    {
        const float* pa = bin_features + (size_t)bi * NDIM * HDIM
                        + (size_t)(warp * 16 + g4) * HDIM + 2 * t4;
#pragma unroll
        for (int ks = 0; ks < 16; ks++) {
            const int k0 = ks * 16;
            afrag[ks * 4 + 0] = f2h2(ldcs2(pa + k0));
            afrag[ks * 4 + 1] = f2h2(ldcs2(pa + 8 * HDIM + k0));
            afrag[ks * 4 + 2] = f2h2(ldcs2(pa + k0 + 8));
            afrag[ks * 4 + 3] = f2h2(ldcs2(pa + 8 * HDIM + k0 + 8));
        }
    }

    __syncthreads();   // ini_s/base_s/wsc_s visible to ALL threads

    const float4* gin  = (const float4*)(inputs + (size_t)b * NDIM * HDIM);
    float4*       gpr  = (float4*)(out_pair + (size_t)bi * NDIM * HDIM);
    const float4* ini4 = (const float4*)ini_s;
    const __half* xwbh = g_xwh + (size_t)(b * NDIM) * HDIM;

    const uint32_t b_lane = (uint32_t)(((lane & 15) * BSTR + ((lane >> 4) << 3)) * 2);

    // per-warp running scores for two j rows (per-thread partials; shuffle at end)
    float sc0 = 0.f, sc1 = 0.f;
    const int j0 = warp * 16 + g4;
    const int j1 = j0 + 8;

    for (int c = 0; c < 8; c++) {
        // atom_pair: this chunk's eighth of the 128KB write (overlaps)
#pragma unroll
        for (int r = 0; r < 4; r++) {
            int g = (c << 10) + t + r * NTHR;
            int j = g >> 6, q = g & 63;
            float4 a = ini4[q];
            float4 x = gin[(j << 6) + q];
            a.x += x.x; a.y += x.y; a.z += x.z; a.w += x.w;
            stcs4(&gpr[g], a);
        }

        asm volatile("cp.async.wait_group 0;" ::: "memory");
        __syncthreads();   // B[c] visible; all warps done reading B[c-1]'s buffer

        // prefetch B chunk c+1 into the other buffer (flies during MMA)
        if (c < 7) {
            const uint32_t dstB = sB[(c + 1) & 1];
#pragma unroll
            for (int it = 0; it < 4; it++) {
                int idx = t + it * NTHR;
                int h = idx >> 2, seg = idx & 3;
                cp_async16(dstB + (uint32_t)(h * BSTR + seg * 8) * 2,
                           &g_Wf[h * HDIM + (c + 1) * 32 + seg * 8]);
            }
            asm volatile("cp.async.commit_group;" ::: "memory");
        }

        const uint32_t curB = sB[c & 1];
        float acc[4][4];
#pragma unroll
        for (int tn = 0; tn < 4; tn++)
#pragma unroll
            for (int e = 0; e < 4; e++) acc[tn][e] = 0.f;

#pragma unroll
        for (int ks = 0; ks < 16; ks++) {
            const int k0 = ks * 16;
            uint32_t bv[2][4];
#pragma unroll
            for (int nt = 0; nt < 2; nt++)
                ldsm_x4_t(bv[nt], curB + b_lane + (uint32_t)((k0 * BSTR + nt * 16) * 2));
#pragma unroll
            for (int tn = 0; tn < 4; tn++) {
                const int nt = tn >> 1, hf = (tn & 1) * 2;
                mma16816(acc[tn], &afrag[ks * 4], &bv[nt][hf]);
            }
        }

        // fused epilogue on fragments (per-thread partial; no shuffles here)
        const int Cb = c * 32;
#pragma unroll
        for (int tn = 0; tn < 4; tn++) {
            const int n0 = Cb + tn * 8 + t4 * 2;
            float2 bw = *(const float2*)&base_s[n0];
            float2 wv = *(const float2*)&wsc_s[n0];
            float2 x0 = __half22float2(*(const __half2*)&xwbh[(size_t)j0 * HDIM + n0]);
            float2 x1 = __half22float2(*(const __half2*)&xwbh[(size_t)j1 * HDIM + n0]);
            const float* a = acc[tn];
            sc0 = fmaf(fmaxf(a[0] + bw.x + x0.x, 0.f), wv.x, sc0);
            sc0 = fmaf(fmaxf(a[1] + bw.y + x0.y, 0.f), wv.y, sc0);
            sc1 = fmaf(fmaxf(a[2] + bw.x + x1.x, 0.f), wv.x, sc1);
            sc1 = fmaf(fmaxf(a[3] + bw.y + x1.y, 0.f), wv.y, sc1);
        }
    }

    // single shuffle reduction over t4 at the end
    sc0 += __shfl_xor_sync(0xffffffffu, sc0, 1);
    sc0 += __shfl_xor_sync(0xffffffffu, sc0, 2);
    sc1 += __shfl_xor_sync(0xffffffffu, sc1, 1);
    sc1 += __shfl_xor_sync(0xffffffffu, sc1, 2);
    if (t4 == 0) {
        score_s[j0] = sc0;
        score_s[j1] = sc1;
    }

    __syncthreads();
    if (t < NDIM) {
        float S = score_s[t];
        S += __shfl_xor_sync(0xffffffffu, S, 16);
        S += __shfl_xor_sync(0xffffffffu, S, 8);
        S += __shfl_xor_sync(0xffffffffu, S, 4);
        S += __shfl_xor_sync(0xffffffffu, S, 2);
        S += __shfl_xor_sync(0xffffffffu, S, 1);
        if ((t & 31) == 0) red_s[t >> 5] = S;
    }
    __syncthreads();
    if (t == 0)
        red_s[4] = red_s[0] + red_s[1] + red_s[2] + red_s[3]
                 + (float)NDIM * b_score[0];
    __syncthreads();

    out_ctx[bi * HDIM + t] = ini_s[t] * red_s[4];
}

// ---------------------------------------------------------------------------
extern "C" void kernel_launch(void* const* d_in, const int* in_sizes, int n_in,
                              void* d_out, int out_size)
{
    const float* inputs       = (const float*)d_in[0];
    const float* bin_features = (const float*)d_in[1];
    const float* W_atom       = (const float*)d_in[2];
    const float* W_bin        = (const float*)d_in[3];
    const float* b_bin        = (const float*)d_in[4];
    const float* w_score      = (const float*)d_in[5];
    const float* b_score      = (const float*)d_in[6];

    float* out_ctx  = (float*)d_out;                   // [B,N,H]
    float* out_pair = out_ctx + BDIM * NDIM * HDIM;    // [B,N,N,H]

    static bool attr_set = false;
    if (!attr_set) {
        cudaFuncSetAttribute(main_kernel, cudaFuncAttributeMaxDynamicSharedMemorySize,
                             SMEM_REQ);
        attr_set = true;
    }

    xw_kernel<<<(BDIM * NDIM) / 4, 256>>>(inputs, W_atom);
    prep_w<<<64, 256>>>(W_bin);
    main_kernel<<<BDIM * NDIM, NTHR, SMEM_REQ>>>(
        inputs, bin_features, b_bin, w_score, b_score, out_ctx, out_pair);
}